// round 1
// baseline (speedup 1.0000x reference)
#include <cuda_runtime.h>
#include <math.h>
#include <float.h>

// Problem shapes (fixed for this problem instance)
#define MM 512          // nodes per frame
#define TT 32           // frames
#define SMAX 262144     // >= S = 200,000
#define NF 4            // smem frame window

// Scratch (static device globals — no allocation allowed)
__device__ int d_hist[TT];
__device__ int d_cursor[TT];
__device__ int d_order[SMAX];
__device__ int d_attach[SMAX];

// ---------------- counting sort by frame ----------------

__global__ void hist_init_kernel() {
    if (threadIdx.x < TT) d_hist[threadIdx.x] = 0;
}

__global__ void hist_kernel(const int* __restrict__ time_index,
                            const int* __restrict__ support_idx, int S) {
    int s = blockIdx.x * blockDim.x + threadIdx.x;
    if (s < S) {
        int t = time_index[support_idx[s]];
        atomicAdd(&d_hist[t], 1);
    }
}

__global__ void scan_kernel() {
    // single thread: 32 bins
    if (threadIdx.x == 0 && blockIdx.x == 0) {
        int acc = 0;
        for (int i = 0; i < TT; i++) { d_cursor[i] = acc; acc += d_hist[i]; }
    }
}

__global__ void scatter_kernel(const int* __restrict__ time_index,
                               const int* __restrict__ support_idx, int S) {
    int s = blockIdx.x * blockDim.x + threadIdx.x;
    if (s < S) {
        int t = time_index[support_idx[s]];
        int pos = atomicAdd(&d_cursor[t], 1);
        d_order[pos] = s;
    }
}

// ---------------- KNN (argmin over M nodes of the point's frame) ----------------

__global__ void __launch_bounds__(256)
knn_kernel(const float* __restrict__ ray_o, const float* __restrict__ ray_d,
           const float* __restrict__ dep_base, const float* __restrict__ dep_c,
           const int* __restrict__ time_index, const int* __restrict__ support_idx,
           const float* __restrict__ node_xyz, int S)
{
    __shared__ float4 snodes[NF * MM];   // (x, y, z, |n|^2) per node, 32KB
    __shared__ int s_flo;

    int pos = blockIdx.x * blockDim.x + threadIdx.x;

    if (threadIdx.x == 0) {
        int s0 = d_order[blockIdx.x * blockDim.x];   // first point of block (always < S)
        s_flo = time_index[support_idx[s0]];
    }
    __syncthreads();
    int f_lo = s_flo;
    int nf = min(NF, TT - f_lo);

    for (int k = threadIdx.x; k < nf * MM; k += blockDim.x) {
        const float* p = node_xyz + ((size_t)f_lo * MM + k) * 3;
        float x = p[0], y = p[1], z = p[2];
        snodes[k] = make_float4(x, y, z, fmaf(z, z, fmaf(y, y, x * x)));
    }
    __syncthreads();

    if (pos >= S) return;
    int s = d_order[pos];
    int i = support_idx[s];
    int t = time_index[i];

    float dep = dep_base[i] + dep_c[i];
    float px = fmaf(ray_d[3 * i + 0], dep, ray_o[3 * i + 0]);
    float py = fmaf(ray_d[3 * i + 1], dep, ray_o[3 * i + 1]);
    float pz = fmaf(ray_d[3 * i + 2], dep, ray_o[3 * i + 2]);
    float xx = fmaf(pz, pz, fmaf(py, py, px * px));

    float best = FLT_MAX;
    int bm = 0;

    if (t >= f_lo && t < f_lo + nf) {
        const float4* nd = snodes + (t - f_lo) * MM;
        #pragma unroll 8
        for (int m = 0; m < MM; m++) {
            float4 n = nd[m];                 // broadcast LDS.128 (warp is frame-coherent)
            float dot = fmaf(pz, n.z, fmaf(py, n.y, px * n.x));
            float d2 = fmaf(-2.0f, dot, xx) + n.w;
            if (d2 < best) { best = d2; bm = m; }
        }
    } else {
        // robustness fallback (block spans > NF frames; statistically never taken)
        for (int m = 0; m < MM; m++) {
            const float* p = node_xyz + ((size_t)t * MM + m) * 3;
            float nx = p[0], ny = p[1], nz = p[2];
            float nn = fmaf(nz, nz, fmaf(ny, ny, nx * nx));
            float dot = fmaf(pz, nz, fmaf(py, ny, px * nx));
            float d2 = fmaf(-2.0f, dot, xx) + nn;
            if (d2 < best) { best = d2; bm = m; }
        }
    }
    d_attach[s] = bm;
}

// ---------------- epilogue: warp + activations + writes (natural order) ----------------

__device__ __forceinline__ void quat2mat_norm(float w, float x, float y, float z, float R[9]) {
    float inv = rsqrtf(fmaf(z, z, fmaf(y, y, fmaf(x, x, w * w))));
    w *= inv; x *= inv; y *= inv; z *= inv;
    R[0] = 1.0f - 2.0f * (y * y + z * z);
    R[1] = 2.0f * (x * y - z * w);
    R[2] = 2.0f * (x * z + y * w);
    R[3] = 2.0f * (x * y + z * w);
    R[4] = 1.0f - 2.0f * (x * x + z * z);
    R[5] = 2.0f * (y * z - x * w);
    R[6] = 2.0f * (x * z - y * w);
    R[7] = 2.0f * (y * z + x * w);
    R[8] = 1.0f - 2.0f * (x * x + y * y);
}

__global__ void __launch_bounds__(256)
epilogue_kernel(const float* __restrict__ ray_o, const float* __restrict__ ray_d,
                const float* __restrict__ dep_base, const float* __restrict__ dep_c,
                const float* __restrict__ quat_w, const float* __restrict__ s_logit,
                const float* __restrict__ o_logit, const float* __restrict__ sph,
                const float* __restrict__ node_xyz, const float* __restrict__ node_quat,
                const int* __restrict__ time_index, const int* __restrict__ support_idx,
                const int* __restrict__ target_t_p, int S, float* __restrict__ out)
{
    int s = blockIdx.x * blockDim.x + threadIdx.x;
    if (s >= S) return;

    int i = support_idx[s];
    int t = time_index[i];
    int tt = target_t_p[0];   // works for int32 or little-endian int64 scalar
    int a = d_attach[s];

    float dep = dep_base[i] + dep_c[i];
    float px = fmaf(ray_d[3 * i + 0], dep, ray_o[3 * i + 0]);
    float py = fmaf(ray_d[3 * i + 1], dep, ray_o[3 * i + 1]);
    float pz = fmaf(ray_d[3 * i + 2], dep, ray_o[3 * i + 2]);

    const float* ps = node_xyz + ((size_t)t * MM + a) * 3;
    const float* pt = node_xyz + ((size_t)tt * MM + a) * 3;
    const float* qs = node_quat + ((size_t)t * MM + a) * 4;
    const float* qt = node_quat + ((size_t)tt * MM + a) * 4;

    // q_rel = q_tgt (x) conj(q_src)   (unnormalized; quat2mat normalizes)
    float aw = qt[0], ax = qt[1], ay = qt[2], az = qt[3];
    float bw = qs[0], bx = -qs[1], by = -qs[2], bz = -qs[3];
    float rw = aw * bw - ax * bx - ay * by - az * bz;
    float rx = aw * bx + ax * bw + ay * bz - az * by;
    float ry = aw * by - ax * bz + ay * bw + az * bx;
    float rz = aw * bz + ax * by - ay * bx + az * bw;

    float R[9];
    quat2mat_norm(rw, rx, ry, rz, R);

    float dx = px - ps[0], dy = py - ps[1], dz = pz - ps[2];
    float mux = fmaf(R[2], dz, fmaf(R[1], dy, R[0] * dx)) + pt[0];
    float muy = fmaf(R[5], dz, fmaf(R[4], dy, R[3] * dx)) + pt[1];
    float muz = fmaf(R[8], dz, fmaf(R[7], dy, R[6] * dx)) + pt[2];

    // fr = R_rel @ R(q_w) = R(q_rel (x) q_w)
    float cw = quat_w[4 * i + 0], cx = quat_w[4 * i + 1];
    float cy = quat_w[4 * i + 2], cz = quat_w[4 * i + 3];
    float fw = rw * cw - rx * cx - ry * cy - rz * cz;
    float fx = rw * cx + rx * cw + ry * cz - rz * cy;
    float fy = rw * cy - rx * cz + ry * cw + rz * cx;
    float fz = rw * cz + rx * cy - ry * cx + rz * cw;
    float F[9];
    quat2mat_norm(fw, fx, fy, fz, F);

    // activations
    float s0 = 0.03f / (1.0f + expf(-s_logit[3 * i + 0]));
    float s1 = 0.03f / (1.0f + expf(-s_logit[3 * i + 1]));
    float s2 = 0.03f / (1.0f + expf(-s_logit[3 * i + 2]));
    float o0 = 1.0f / (1.0f + expf(-o_logit[i]));
    float h0 = sph[3 * i + 0], h1 = sph[3 * i + 1], h2 = sph[3 * i + 2];

    // output layout: mu[S*3] | fr[S*9] | s[S*3] | o[S] | sph[S*27]
    size_t Sz = (size_t)S;
    float* mu_o  = out;
    float* fr_o  = out + 3 * Sz;
    float* ss_o  = out + 12 * Sz;
    float* oo_o  = out + 15 * Sz;
    float* sph_o = out + 16 * Sz;

    mu_o[3 * s + 0] = mux; mu_o[3 * s + 1] = muy; mu_o[3 * s + 2] = muz;
    #pragma unroll
    for (int k = 0; k < 9; k++) fr_o[9 * s + k] = F[k];
    ss_o[3 * s + 0] = s0; ss_o[3 * s + 1] = s1; ss_o[3 * s + 2] = s2;
    oo_o[s] = o0;
    sph_o[27 * s + 0] = h0; sph_o[27 * s + 1] = h1; sph_o[27 * s + 2] = h2;
    #pragma unroll
    for (int k = 3; k < 27; k++) sph_o[27 * s + k] = 0.0f;
}

// ---------------- launch ----------------

extern "C" void kernel_launch(void* const* d_in, const int* in_sizes, int n_in,
                              void* d_out, int out_size)
{
    const float* ray_o      = (const float*)d_in[0];
    const float* ray_d      = (const float*)d_in[1];
    const float* dep_base   = (const float*)d_in[2];
    const float* dep_c      = (const float*)d_in[3];
    const float* quat_w     = (const float*)d_in[4];
    const float* s_logit    = (const float*)d_in[5];
    const float* o_logit    = (const float*)d_in[6];
    const float* sph        = (const float*)d_in[7];
    const float* node_xyz   = (const float*)d_in[8];
    const float* node_quat  = (const float*)d_in[9];
    const int*   time_index = (const int*)d_in[10];
    const int*   support_idx= (const int*)d_in[11];
    const int*   target_t   = (const int*)d_in[12];

    int S = in_sizes[11];
    int blocks = (S + 255) / 256;

    hist_init_kernel<<<1, TT>>>();
    hist_kernel<<<blocks, 256>>>(time_index, support_idx, S);
    scan_kernel<<<1, 1>>>();
    scatter_kernel<<<blocks, 256>>>(time_index, support_idx, S);
    knn_kernel<<<blocks, 256>>>(ray_o, ray_d, dep_base, dep_c,
                                time_index, support_idx, node_xyz, S);
    epilogue_kernel<<<blocks, 256>>>(ray_o, ray_d, dep_base, dep_c,
                                     quat_w, s_logit, o_logit, sph,
                                     node_xyz, node_quat, time_index, support_idx,
                                     target_t, S, (float*)d_out);
}

// round 2
// speedup vs baseline: 1.5847x; 1.5847x over previous
#include <cuda_runtime.h>
#include <math.h>
#include <float.h>

// Problem shapes (fixed for this problem instance)
#define MM 512          // nodes per frame
#define TT 32           // frames
#define SMAX 262144     // >= S = 200,000
#define NF 4            // smem frame window
#define BMAXB 1024      // max blocks of 256 over SMAX

// Scratch (static device globals — no allocation allowed)
__device__ int d_blockHist[TT * BMAXB];  // exclusive-prefix-within-bin after scan
__device__ int d_binBase[TT];
__device__ int d_order[SMAX];
__device__ int d_attach[SMAX];
__device__ int d_tval[SMAX];             // cached t per support point

// ---------------- phase A: per-block histogram (smem atomics only) ----------------

__global__ void __launch_bounds__(256)
hist_kernel(const int* __restrict__ time_index,
            const int* __restrict__ support_idx, int S)
{
    __shared__ int h[TT];
    if (threadIdx.x < TT) h[threadIdx.x] = 0;
    __syncthreads();

    int s = blockIdx.x * blockDim.x + threadIdx.x;
    if (s < S) {
        int t = time_index[support_idx[s]];
        d_tval[s] = t;
        atomicAdd(&h[t], 1);
    }
    __syncthreads();
    if (threadIdx.x < TT)
        d_blockHist[threadIdx.x * BMAXB + blockIdx.x] = h[threadIdx.x];
}

// ---------------- phase B: scan (single block, one warp per bin) ----------------

__global__ void __launch_bounds__(1024)
scan_kernel(int B)
{
    __shared__ int binTotal[TT];
    int w = threadIdx.x >> 5;          // bin
    int lane = threadIdx.x & 31;

    int run = 0;
    for (int base = 0; base < B; base += 32) {
        int idx = base + lane;
        int v = (idx < B) ? d_blockHist[w * BMAXB + idx] : 0;
        int incl = v;
        #pragma unroll
        for (int o = 1; o < 32; o <<= 1) {
            int n = __shfl_up_sync(0xFFFFFFFFu, incl, o);
            if (lane >= o) incl += n;
        }
        if (idx < B) d_blockHist[w * BMAXB + idx] = run + incl - v;  // exclusive within bin
        run += __shfl_sync(0xFFFFFFFFu, incl, 31);
    }
    if (lane == 0) binTotal[w] = run;
    __syncthreads();

    if (threadIdx.x < TT) {
        int v = binTotal[threadIdx.x];
        int incl = v;
        #pragma unroll
        for (int o = 1; o < 32; o <<= 1) {
            int n = __shfl_up_sync(0xFFFFFFFFu, incl, o);
            if ((threadIdx.x & 31) >= o) incl += n;
        }
        d_binBase[threadIdx.x] = incl - v;   // exclusive over bins
    }
}

// ---------------- phase C: scatter (smem cursors, no global atomics) ----------------

__global__ void __launch_bounds__(256)
scatter_kernel(int S)
{
    __shared__ int cur[TT];
    __shared__ int basebin[TT];
    if (threadIdx.x < TT) {
        cur[threadIdx.x] = 0;
        basebin[threadIdx.x] = d_blockHist[threadIdx.x * BMAXB + blockIdx.x]
                             + d_binBase[threadIdx.x];
    }
    __syncthreads();

    int s = blockIdx.x * blockDim.x + threadIdx.x;
    if (s < S) {
        int t = d_tval[s];
        int r = atomicAdd(&cur[t], 1);
        d_order[basebin[t] + r] = s;
    }
}

// ---------------- KNN (argmin over M nodes of the point's frame) ----------------

__global__ void __launch_bounds__(256)
knn_kernel(const float* __restrict__ ray_o, const float* __restrict__ ray_d,
           const float* __restrict__ dep_base, const float* __restrict__ dep_c,
           const int* __restrict__ support_idx,
           const float* __restrict__ node_xyz, int S)
{
    __shared__ float4 snodes[NF * MM];   // (x, y, z, |n|^2) per node, 32KB
    __shared__ int s_flo;

    int pos = blockIdx.x * blockDim.x + threadIdx.x;

    if (threadIdx.x == 0) {
        int s0 = d_order[blockIdx.x * blockDim.x];   // first point of block (always < S)
        s_flo = d_tval[s0];
    }
    __syncthreads();
    int f_lo = s_flo;
    int nf = min(NF, TT - f_lo);

    for (int k = threadIdx.x; k < nf * MM; k += blockDim.x) {
        const float* p = node_xyz + ((size_t)f_lo * MM + k) * 3;
        float x = p[0], y = p[1], z = p[2];
        snodes[k] = make_float4(x, y, z, fmaf(z, z, fmaf(y, y, x * x)));
    }
    __syncthreads();

    if (pos >= S) return;
    int s = d_order[pos];
    int i = support_idx[s];
    int t = d_tval[s];

    float dep = dep_base[i] + dep_c[i];
    float px = fmaf(ray_d[3 * i + 0], dep, ray_o[3 * i + 0]);
    float py = fmaf(ray_d[3 * i + 1], dep, ray_o[3 * i + 1]);
    float pz = fmaf(ray_d[3 * i + 2], dep, ray_o[3 * i + 2]);
    float xx = fmaf(pz, pz, fmaf(py, py, px * px));

    float best = FLT_MAX;
    int bm = 0;

    if (t >= f_lo && t < f_lo + nf) {
        const float4* nd = snodes + (t - f_lo) * MM;
        #pragma unroll 8
        for (int m = 0; m < MM; m++) {
            float4 n = nd[m];                 // broadcast LDS.128 (warp is frame-coherent)
            float dot = fmaf(pz, n.z, fmaf(py, n.y, px * n.x));
            float d2 = fmaf(-2.0f, dot, xx) + n.w;
            if (d2 < best) { best = d2; bm = m; }
        }
    } else {
        // robustness fallback (block spans > NF frames; statistically never taken)
        for (int m = 0; m < MM; m++) {
            const float* p = node_xyz + ((size_t)t * MM + m) * 3;
            float nx = p[0], ny = p[1], nz = p[2];
            float nn = fmaf(nz, nz, fmaf(ny, ny, nx * nx));
            float dot = fmaf(pz, nz, fmaf(py, ny, px * nx));
            float d2 = fmaf(-2.0f, dot, xx) + nn;
            if (d2 < best) { best = d2; bm = m; }
        }
    }
    d_attach[s] = bm;
}

// ---------------- epilogue: warp + activations + writes (natural order) ----------------

__device__ __forceinline__ void quat2mat_norm(float w, float x, float y, float z, float R[9]) {
    float inv = rsqrtf(fmaf(z, z, fmaf(y, y, fmaf(x, x, w * w))));
    w *= inv; x *= inv; y *= inv; z *= inv;
    R[0] = 1.0f - 2.0f * (y * y + z * z);
    R[1] = 2.0f * (x * y - z * w);
    R[2] = 2.0f * (x * z + y * w);
    R[3] = 2.0f * (x * y + z * w);
    R[4] = 1.0f - 2.0f * (x * x + z * z);
    R[5] = 2.0f * (y * z - x * w);
    R[6] = 2.0f * (x * z - y * w);
    R[7] = 2.0f * (y * z + x * w);
    R[8] = 1.0f - 2.0f * (x * x + y * y);
}

__global__ void __launch_bounds__(256)
epilogue_kernel(const float* __restrict__ ray_o, const float* __restrict__ ray_d,
                const float* __restrict__ dep_base, const float* __restrict__ dep_c,
                const float* __restrict__ quat_w, const float* __restrict__ s_logit,
                const float* __restrict__ o_logit, const float* __restrict__ sph,
                const float* __restrict__ node_xyz, const float* __restrict__ node_quat,
                const int* __restrict__ support_idx,
                const int* __restrict__ target_t_p, int S, float* __restrict__ out)
{
    int s = blockIdx.x * blockDim.x + threadIdx.x;
    if (s >= S) return;

    int i = support_idx[s];
    int t = d_tval[s];
    int tt = target_t_p[0];
    int a = d_attach[s];

    float dep = dep_base[i] + dep_c[i];
    float px = fmaf(ray_d[3 * i + 0], dep, ray_o[3 * i + 0]);
    float py = fmaf(ray_d[3 * i + 1], dep, ray_o[3 * i + 1]);
    float pz = fmaf(ray_d[3 * i + 2], dep, ray_o[3 * i + 2]);

    const float* ps = node_xyz + ((size_t)t * MM + a) * 3;
    const float* pt = node_xyz + ((size_t)tt * MM + a) * 3;
    const float* qs = node_quat + ((size_t)t * MM + a) * 4;
    const float* qt = node_quat + ((size_t)tt * MM + a) * 4;

    // q_rel = q_tgt (x) conj(q_src)   (unnormalized; quat2mat normalizes)
    float aw = qt[0], ax = qt[1], ay = qt[2], az = qt[3];
    float bw = qs[0], bx = -qs[1], by = -qs[2], bz = -qs[3];
    float rw = aw * bw - ax * bx - ay * by - az * bz;
    float rx = aw * bx + ax * bw + ay * bz - az * by;
    float ry = aw * by - ax * bz + ay * bw + az * bx;
    float rz = aw * bz + ax * by - ay * bx + az * bw;

    float R[9];
    quat2mat_norm(rw, rx, ry, rz, R);

    float dx = px - ps[0], dy = py - ps[1], dz = pz - ps[2];
    float mux = fmaf(R[2], dz, fmaf(R[1], dy, R[0] * dx)) + pt[0];
    float muy = fmaf(R[5], dz, fmaf(R[4], dy, R[3] * dx)) + pt[1];
    float muz = fmaf(R[8], dz, fmaf(R[7], dy, R[6] * dx)) + pt[2];

    // fr = R_rel @ R(q_w) = R(q_rel (x) q_w)
    float cw = quat_w[4 * i + 0], cx = quat_w[4 * i + 1];
    float cy = quat_w[4 * i + 2], cz = quat_w[4 * i + 3];
    float fw = rw * cw - rx * cx - ry * cy - rz * cz;
    float fx = rw * cx + rx * cw + ry * cz - rz * cy;
    float fy = rw * cy - rx * cz + ry * cw + rz * cx;
    float fz = rw * cz + rx * cy - ry * cx + rz * cw;
    float F[9];
    quat2mat_norm(fw, fx, fy, fz, F);

    // activations
    float s0 = 0.03f / (1.0f + expf(-s_logit[3 * i + 0]));
    float s1 = 0.03f / (1.0f + expf(-s_logit[3 * i + 1]));
    float s2 = 0.03f / (1.0f + expf(-s_logit[3 * i + 2]));
    float o0 = 1.0f / (1.0f + expf(-o_logit[i]));
    float h0 = sph[3 * i + 0], h1 = sph[3 * i + 1], h2 = sph[3 * i + 2];

    // output layout: mu[S*3] | fr[S*9] | s[S*3] | o[S] | sph[S*27]
    size_t Sz = (size_t)S;
    float* mu_o  = out;
    float* fr_o  = out + 3 * Sz;
    float* ss_o  = out + 12 * Sz;
    float* oo_o  = out + 15 * Sz;
    float* sph_o = out + 16 * Sz;

    mu_o[3 * s + 0] = mux; mu_o[3 * s + 1] = muy; mu_o[3 * s + 2] = muz;
    #pragma unroll
    for (int k = 0; k < 9; k++) fr_o[9 * s + k] = F[k];
    ss_o[3 * s + 0] = s0; ss_o[3 * s + 1] = s1; ss_o[3 * s + 2] = s2;
    oo_o[s] = o0;
    sph_o[27 * s + 0] = h0; sph_o[27 * s + 1] = h1; sph_o[27 * s + 2] = h2;
    #pragma unroll
    for (int k = 3; k < 27; k++) sph_o[27 * s + k] = 0.0f;
}

// ---------------- launch ----------------

extern "C" void kernel_launch(void* const* d_in, const int* in_sizes, int n_in,
                              void* d_out, int out_size)
{
    const float* ray_o      = (const float*)d_in[0];
    const float* ray_d      = (const float*)d_in[1];
    const float* dep_base   = (const float*)d_in[2];
    const float* dep_c      = (const float*)d_in[3];
    const float* quat_w     = (const float*)d_in[4];
    const float* s_logit    = (const float*)d_in[5];
    const float* o_logit    = (const float*)d_in[6];
    const float* sph        = (const float*)d_in[7];
    const float* node_xyz   = (const float*)d_in[8];
    const float* node_quat  = (const float*)d_in[9];
    const int*   time_index = (const int*)d_in[10];
    const int*   support_idx= (const int*)d_in[11];
    const int*   target_t   = (const int*)d_in[12];

    int S = in_sizes[11];
    int blocks = (S + 255) / 256;

    hist_kernel<<<blocks, 256>>>(time_index, support_idx, S);
    scan_kernel<<<1, 1024>>>(blocks);
    scatter_kernel<<<blocks, 256>>>(S);
    knn_kernel<<<blocks, 256>>>(ray_o, ray_d, dep_base, dep_c,
                                support_idx, node_xyz, S);
    epilogue_kernel<<<blocks, 256>>>(ray_o, ray_d, dep_base, dep_c,
                                     quat_w, s_logit, o_logit, sph,
                                     node_xyz, node_quat, support_idx,
                                     target_t, S, (float*)d_out);
}

// round 3
// speedup vs baseline: 2.5279x; 1.5952x over previous
#include <cuda_runtime.h>
#include <math.h>
#include <float.h>

// Problem shapes (fixed for this problem instance)
#define MM 512          // nodes per frame
#define TT 32           // frames
#define SMAX 262144     // >= S = 200,000
#define NF 2            // smem frame window
#define BMAXB 1024      // max blocks of 256 over SMAX

// Scratch (static device globals — no allocation allowed)
__device__ int d_blockHist[TT * BMAXB];  // exclusive-prefix-within-bin after scan
__device__ int d_binBase[TT];
__device__ int d_order[SMAX];
__device__ int d_attach[SMAX];
__device__ int d_tval[SMAX];             // cached t per support point

// ---------------- phase A: per-block histogram + sph zero-fill ----------------

__global__ void __launch_bounds__(256)
hist_kernel(const int* __restrict__ time_index,
            const int* __restrict__ support_idx, int S,
            float4* __restrict__ zbase, int nz4)
{
    __shared__ int h[TT];
    if (threadIdx.x < TT) h[threadIdx.x] = 0;
    __syncthreads();

    int s = blockIdx.x * blockDim.x + threadIdx.x;
    if (s < S) {
        int t = time_index[support_idx[s]];
        d_tval[s] = t;
        atomicAdd(&h[t], 1);
    }
    __syncthreads();
    if (threadIdx.x < TT)
        d_blockHist[threadIdx.x * BMAXB + blockIdx.x] = h[threadIdx.x];

    // coalesced zero-fill of the sph output region (overwritten later for live lanes)
    const float4 z = make_float4(0.f, 0.f, 0.f, 0.f);
    int nthreads = gridDim.x * blockDim.x;
    for (int k = blockIdx.x * blockDim.x + threadIdx.x; k < nz4; k += nthreads)
        zbase[k] = z;
}

// ---------------- phase B: scan (single block, one warp per bin) ----------------

__global__ void __launch_bounds__(1024)
scan_kernel(int B)
{
    __shared__ int binTotal[TT];
    int w = threadIdx.x >> 5;          // bin
    int lane = threadIdx.x & 31;

    int run = 0;
    for (int base = 0; base < B; base += 32) {
        int idx = base + lane;
        int v = (idx < B) ? d_blockHist[w * BMAXB + idx] : 0;
        int incl = v;
        #pragma unroll
        for (int o = 1; o < 32; o <<= 1) {
            int n = __shfl_up_sync(0xFFFFFFFFu, incl, o);
            if (lane >= o) incl += n;
        }
        if (idx < B) d_blockHist[w * BMAXB + idx] = run + incl - v;  // exclusive within bin
        run += __shfl_sync(0xFFFFFFFFu, incl, 31);
    }
    if (lane == 0) binTotal[w] = run;
    __syncthreads();

    if (threadIdx.x < TT) {
        int v = binTotal[threadIdx.x];
        int incl = v;
        #pragma unroll
        for (int o = 1; o < 32; o <<= 1) {
            int n = __shfl_up_sync(0xFFFFFFFFu, incl, o);
            if ((threadIdx.x & 31) >= o) incl += n;
        }
        d_binBase[threadIdx.x] = incl - v;   // exclusive over bins
    }
}

// ---------------- phase C: scatter (smem cursors, no global atomics) ----------------

__global__ void __launch_bounds__(256)
scatter_kernel(int S)
{
    __shared__ int cur[TT];
    __shared__ int basebin[TT];
    if (threadIdx.x < TT) {
        cur[threadIdx.x] = 0;
        basebin[threadIdx.x] = d_blockHist[threadIdx.x * BMAXB + blockIdx.x]
                             + d_binBase[threadIdx.x];
    }
    __syncthreads();

    int s = blockIdx.x * blockDim.x + threadIdx.x;
    if (s < S) {
        int t = d_tval[s];
        int r = atomicAdd(&cur[t], 1);
        d_order[basebin[t] + r] = s;
    }
}

// ---------------- KNN (argmin over M nodes of the point's frame) ----------------

__global__ void __launch_bounds__(256)
knn_kernel(const float* __restrict__ ray_o, const float* __restrict__ ray_d,
           const float* __restrict__ dep_base, const float* __restrict__ dep_c,
           const int* __restrict__ support_idx,
           const float* __restrict__ node_xyz, int S)
{
    __shared__ float4 snodes[NF * MM];   // (x, y, z, |n|^2) per node, 16.5KB
    __shared__ int s_flo;

    int pos = blockIdx.x * blockDim.x + threadIdx.x;

    if (threadIdx.x == 0) {
        int s0 = d_order[blockIdx.x * blockDim.x];   // first point of block (always < S)
        s_flo = d_tval[s0];
    }
    __syncthreads();
    int f_lo = s_flo;
    int nf = min(NF, TT - f_lo);

    for (int k = threadIdx.x; k < nf * MM; k += blockDim.x) {
        const float* p = node_xyz + ((size_t)f_lo * MM + k) * 3;
        float x = p[0], y = p[1], z = p[2];
        snodes[k] = make_float4(x, y, z, fmaf(z, z, fmaf(y, y, x * x)));
    }
    __syncthreads();

    if (pos >= S) return;
    int s = d_order[pos];
    int i = support_idx[s];
    int t = d_tval[s];

    float dep = dep_base[i] + dep_c[i];
    float px = fmaf(ray_d[3 * i + 0], dep, ray_o[3 * i + 0]);
    float py = fmaf(ray_d[3 * i + 1], dep, ray_o[3 * i + 1]);
    float pz = fmaf(ray_d[3 * i + 2], dep, ray_o[3 * i + 2]);
    // score(m) = |n|^2 - 2 p.n  (argmin-equivalent: the per-point |p|^2 constant is dropped)
    float qx = -2.0f * px, qy = -2.0f * py, qz = -2.0f * pz;

    int bm;

    if (t >= f_lo && t < f_lo + nf) {
        const float4* nd = snodes + (t - f_lo) * MM;
        // 4 independent accumulators over contiguous chunks: breaks the serial
        // compare chain while preserving first-occurrence tie semantics.
        float b0 = FLT_MAX, b1 = FLT_MAX, b2 = FLT_MAX, b3 = FLT_MAX;
        int i0 = 0, i1 = 128, i2 = 256, i3 = 384;
        #pragma unroll 4
        for (int m = 0; m < 128; m++) {
            float4 n0 = nd[m];
            float4 n1 = nd[m + 128];
            float4 n2 = nd[m + 256];
            float4 n3 = nd[m + 384];
            float s0 = fmaf(qz, n0.z, fmaf(qy, n0.y, fmaf(qx, n0.x, n0.w)));
            float s1 = fmaf(qz, n1.z, fmaf(qy, n1.y, fmaf(qx, n1.x, n1.w)));
            float s2 = fmaf(qz, n2.z, fmaf(qy, n2.y, fmaf(qx, n2.x, n2.w)));
            float s3 = fmaf(qz, n3.z, fmaf(qy, n3.y, fmaf(qx, n3.x, n3.w)));
            if (s0 < b0) { b0 = s0; i0 = m; }
            if (s1 < b1) { b1 = s1; i1 = m + 128; }
            if (s2 < b2) { b2 = s2; i2 = m + 256; }
            if (s3 < b3) { b3 = s3; i3 = m + 384; }
        }
        float best = b0; bm = i0;
        if (b1 < best) { best = b1; bm = i1; }
        if (b2 < best) { best = b2; bm = i2; }
        if (b3 < best) { best = b3; bm = i3; }
    } else {
        // robustness fallback (block spans > NF frames; statistically never taken)
        float best = FLT_MAX; bm = 0;
        for (int m = 0; m < MM; m++) {
            const float* p = node_xyz + ((size_t)t * MM + m) * 3;
            float nx = p[0], ny = p[1], nz = p[2];
            float nn = fmaf(nz, nz, fmaf(ny, ny, nx * nx));
            float sc = fmaf(qz, nz, fmaf(qy, ny, fmaf(qx, nx, nn)));
            if (sc < best) { best = sc; bm = m; }
        }
    }
    d_attach[s] = bm;
}

// ---------------- epilogue: warp + activations + writes (natural order) ----------------

__device__ __forceinline__ void quat2mat_norm(float w, float x, float y, float z, float R[9]) {
    float inv = rsqrtf(fmaf(z, z, fmaf(y, y, fmaf(x, x, w * w))));
    w *= inv; x *= inv; y *= inv; z *= inv;
    R[0] = 1.0f - 2.0f * (y * y + z * z);
    R[1] = 2.0f * (x * y - z * w);
    R[2] = 2.0f * (x * z + y * w);
    R[3] = 2.0f * (x * y + z * w);
    R[4] = 1.0f - 2.0f * (x * x + z * z);
    R[5] = 2.0f * (y * z - x * w);
    R[6] = 2.0f * (x * z - y * w);
    R[7] = 2.0f * (y * z + x * w);
    R[8] = 1.0f - 2.0f * (x * x + y * y);
}

__device__ __forceinline__ float fast_sigmoid(float x) {
    return 1.0f / (1.0f + __expf(-x));
}

__global__ void __launch_bounds__(256)
epilogue_kernel(const float* __restrict__ ray_o, const float* __restrict__ ray_d,
                const float* __restrict__ dep_base, const float* __restrict__ dep_c,
                const float* __restrict__ quat_w, const float* __restrict__ s_logit,
                const float* __restrict__ o_logit, const float* __restrict__ sph,
                const float* __restrict__ node_xyz, const float* __restrict__ node_quat,
                const int* __restrict__ support_idx,
                const int* __restrict__ target_t_p, int S, float* __restrict__ out)
{
    int s = blockIdx.x * blockDim.x + threadIdx.x;
    if (s >= S) return;

    int i = support_idx[s];
    int t = d_tval[s];
    int tt = target_t_p[0];
    int a = d_attach[s];

    float dep = dep_base[i] + dep_c[i];
    float px = fmaf(ray_d[3 * i + 0], dep, ray_o[3 * i + 0]);
    float py = fmaf(ray_d[3 * i + 1], dep, ray_o[3 * i + 1]);
    float pz = fmaf(ray_d[3 * i + 2], dep, ray_o[3 * i + 2]);

    const float* ps = node_xyz + ((size_t)t * MM + a) * 3;
    const float* pt = node_xyz + ((size_t)tt * MM + a) * 3;
    float4 qsv = ((const float4*)node_quat)[(size_t)t * MM + a];
    float4 qtv = ((const float4*)node_quat)[(size_t)tt * MM + a];

    // q_rel = q_tgt (x) conj(q_src)   (unnormalized; quat2mat normalizes)
    float aw = qtv.x, ax = qtv.y, ay = qtv.z, az = qtv.w;
    float bw = qsv.x, bx = -qsv.y, by = -qsv.z, bz = -qsv.w;
    float rw = aw * bw - ax * bx - ay * by - az * bz;
    float rx = aw * bx + ax * bw + ay * bz - az * by;
    float ry = aw * by - ax * bz + ay * bw + az * bx;
    float rz = aw * bz + ax * by - ay * bx + az * bw;

    float R[9];
    quat2mat_norm(rw, rx, ry, rz, R);

    float dx = px - ps[0], dy = py - ps[1], dz = pz - ps[2];
    float mux = fmaf(R[2], dz, fmaf(R[1], dy, R[0] * dx)) + pt[0];
    float muy = fmaf(R[5], dz, fmaf(R[4], dy, R[3] * dx)) + pt[1];
    float muz = fmaf(R[8], dz, fmaf(R[7], dy, R[6] * dx)) + pt[2];

    // fr = R_rel @ R(q_w) = R(q_rel (x) q_w)
    float4 qcv = ((const float4*)quat_w)[i];
    float cw = qcv.x, cx = qcv.y, cy = qcv.z, cz = qcv.w;
    float fw = rw * cw - rx * cx - ry * cy - rz * cz;
    float fx = rw * cx + rx * cw + ry * cz - rz * cy;
    float fy = rw * cy - rx * cz + ry * cw + rz * cx;
    float fz = rw * cz + rx * cy - ry * cx + rz * cw;
    float F[9];
    quat2mat_norm(fw, fx, fy, fz, F);

    // activations
    float s0 = 0.03f * fast_sigmoid(s_logit[3 * i + 0]);
    float s1 = 0.03f * fast_sigmoid(s_logit[3 * i + 1]);
    float s2 = 0.03f * fast_sigmoid(s_logit[3 * i + 2]);
    float o0 = fast_sigmoid(o_logit[i]);
    float h0 = sph[3 * i + 0], h1 = sph[3 * i + 1], h2 = sph[3 * i + 2];

    // output layout: mu[S*3] | fr[S*9] | s[S*3] | o[S] | sph[S*27]
    size_t Sz = (size_t)S;
    float* mu_o  = out;
    float* fr_o  = out + 3 * Sz;
    float* ss_o  = out + 12 * Sz;
    float* oo_o  = out + 15 * Sz;
    float* sph_o = out + 16 * Sz;

    mu_o[3 * s + 0] = mux; mu_o[3 * s + 1] = muy; mu_o[3 * s + 2] = muz;
    #pragma unroll
    for (int k = 0; k < 9; k++) fr_o[9 * s + k] = F[k];
    ss_o[3 * s + 0] = s0; ss_o[3 * s + 1] = s1; ss_o[3 * s + 2] = s2;
    oo_o[s] = o0;
    // tail [3..27) already zero-filled by hist_kernel
    sph_o[27 * s + 0] = h0; sph_o[27 * s + 1] = h1; sph_o[27 * s + 2] = h2;
}

// ---------------- launch ----------------

extern "C" void kernel_launch(void* const* d_in, const int* in_sizes, int n_in,
                              void* d_out, int out_size)
{
    const float* ray_o      = (const float*)d_in[0];
    const float* ray_d      = (const float*)d_in[1];
    const float* dep_base   = (const float*)d_in[2];
    const float* dep_c      = (const float*)d_in[3];
    const float* quat_w     = (const float*)d_in[4];
    const float* s_logit    = (const float*)d_in[5];
    const float* o_logit    = (const float*)d_in[6];
    const float* sph        = (const float*)d_in[7];
    const float* node_xyz   = (const float*)d_in[8];
    const float* node_quat  = (const float*)d_in[9];
    const int*   time_index = (const int*)d_in[10];
    const int*   support_idx= (const int*)d_in[11];
    const int*   target_t   = (const int*)d_in[12];

    int S = in_sizes[11];
    int blocks = (S + 255) / 256;

    // sph region: floats [16S, 43S) — 27S floats, 16S is divisible by 4 when S is even
    float* zstart = (float*)d_out + 16 * (size_t)S;
    int nz4 = (27 * S) / 4;   // S = 200000 -> divisible by 4

    hist_kernel<<<blocks, 256>>>(time_index, support_idx, S, (float4*)zstart, nz4);
    scan_kernel<<<1, 1024>>>(blocks);
    scatter_kernel<<<blocks, 256>>>(S);
    knn_kernel<<<blocks, 256>>>(ray_o, ray_d, dep_base, dep_c,
                                support_idx, node_xyz, S);
    epilogue_kernel<<<blocks, 256>>>(ray_o, ray_d, dep_base, dep_c,
                                     quat_w, s_logit, o_logit, sph,
                                     node_xyz, node_quat, support_idx,
                                     target_t, S, (float*)d_out);
}